// round 1
// baseline (speedup 1.0000x reference)
#include <cuda_runtime.h>
#include <cuda_bf16.h>

// ----------------------------------------------------------------------------
// StableQGFD layer: Q/K/V proj -> scores softmax (p0), K-sim softmax (P),
// 2-step diffusion p <- 0.95*p0 + 0.05*p@P, attn = p@V, out = attn@Wo + bo.
// Outputs: out [2048,1024] then p [16,2048,2048] concatenated in d_out.
// All GEMMs: TF32 mma.sync (fp32 in/out, rna-rounded tf32 operands).
// ----------------------------------------------------------------------------

#define N_TOK 2048
#define D_EMB 1024
#define N_HEAD 16
#define HD 64

// Scratch (allocation-free rule: __device__ globals)
__device__ float g_q[(size_t)N_TOK * D_EMB];
__device__ float g_k[(size_t)N_TOK * D_EMB];
__device__ float g_v[(size_t)N_TOK * D_EMB];
__device__ float g_attn[(size_t)N_TOK * D_EMB];
__device__ float g_p0[(size_t)N_HEAD * N_TOK * N_TOK];
__device__ float g_P [(size_t)N_HEAD * N_TOK * N_TOK];
__device__ float g_p1[(size_t)N_HEAD * N_TOK * N_TOK];
__device__ float g_p2[(size_t)N_HEAD * N_TOK * N_TOK];

__device__ __forceinline__ float f2tf32(float x) {
    asm("cvt.rna.tf32.f32 %0, %0;" : "+f"(x));
    return x;
}

__device__ __forceinline__ void mma_tf32(float* c, const float4& a, const float2& b) {
    unsigned a0 = __float_as_uint(a.x), a1 = __float_as_uint(a.y);
    unsigned a2 = __float_as_uint(a.z), a3 = __float_as_uint(a.w);
    unsigned b0 = __float_as_uint(b.x), b1 = __float_as_uint(b.y);
    asm volatile(
        "mma.sync.aligned.m16n8k8.row.col.f32.tf32.tf32.f32 "
        "{%0,%1,%2,%3},{%4,%5,%6,%7},{%8,%9},{%0,%1,%2,%3};"
        : "+f"(c[0]), "+f"(c[1]), "+f"(c[2]), "+f"(c[3])
        : "r"(a0), "r"(a1), "r"(a2), "r"(a3), "r"(b0), "r"(b1));
}

// C[M,N] = alpha * A@B(^T) + beta*SRC + bias, fp32 io, tf32 compute.
// TB=false: B is [K,N] row-major (NN). TB=true: B is [N,K] row-major (NT).
// blockIdx.z batches heads via element strides sA/sB/sC/sS.
// Requires: M % BM == 0, N % BN == 0, K % 16 == 0, lda/ldb/ldc % 4 == 0,
// all base offsets 16B aligned.
template <int BM, int BN, int WM, int WN, bool TB>
__global__ void __launch_bounds__((BM / WM) * (BN / WN) * 32, 2)
gemm_tf32_kernel(const float* __restrict__ A, const float* __restrict__ B,
                 const float* __restrict__ SRC, const float* __restrict__ bias,
                 float* __restrict__ C,
                 int K, int lda, int ldb, int ldc,
                 long long sA, long long sB, long long sC, long long sS,
                 float alpha, float beta) {
    constexpr int BK = 16;
    constexpr int THREADS = (BM / WM) * (BN / WN) * 32;
    constexpr int MA = WM / 16;
    constexpr int NA = WN / 8;
    constexpr int AS_STRIDE = BK + 4;                 // conflict-free for frag reads
    constexpr int BS_ROWS   = TB ? BN : BK;
    constexpr int BS_STRIDE = TB ? (BK + 4) : (BN + 8);

    __shared__ float As[BM * AS_STRIDE];
    __shared__ float Bs[BS_ROWS * BS_STRIDE];

    const int z = blockIdx.z;
    A += (long long)z * sA;
    B += (long long)z * sB;
    C += (long long)z * sC;
    const float* S = SRC ? SRC + (long long)z * sS : nullptr;

    const int m0 = blockIdx.y * BM;
    const int n0 = blockIdx.x * BN;
    const int tid = threadIdx.x;
    const int lane = tid & 31, warp = tid >> 5;
    constexpr int WARPS_N = BN / WN;
    const int wm = (warp / WARPS_N) * WM;
    const int wn = (warp % WARPS_N) * WN;
    const int lr = lane >> 2;   // 0..7
    const int lc = lane & 3;    // 0..3

    float acc[MA][NA][4];
#pragma unroll
    for (int i = 0; i < MA; i++)
#pragma unroll
        for (int j = 0; j < NA; j++) {
            acc[i][j][0] = 0.f; acc[i][j][1] = 0.f;
            acc[i][j][2] = 0.f; acc[i][j][3] = 0.f;
        }

    for (int k0 = 0; k0 < K; k0 += BK) {
        // ---- load A tile [BM x 16] (tf32-rounded) ----
        constexpr int AIT = (BM * BK) / (THREADS * 4);
#pragma unroll
        for (int t = 0; t < AIT; t++) {
            int idx = tid + t * THREADS;
            int r = idx >> 2, q = idx & 3;
            float4 vv = *reinterpret_cast<const float4*>(
                A + (long long)(m0 + r) * lda + k0 + q * 4);
            vv.x = f2tf32(vv.x); vv.y = f2tf32(vv.y);
            vv.z = f2tf32(vv.z); vv.w = f2tf32(vv.w);
            *reinterpret_cast<float4*>(&As[r * AS_STRIDE + q * 4]) = vv;
        }
        // ---- load B tile ----
        if (TB) {
            constexpr int BIT = (BN * BK) / (THREADS * 4);
#pragma unroll
            for (int t = 0; t < BIT; t++) {
                int idx = tid + t * THREADS;
                int r = idx >> 2, q = idx & 3;
                float4 vv = *reinterpret_cast<const float4*>(
                    B + (long long)(n0 + r) * ldb + k0 + q * 4);
                vv.x = f2tf32(vv.x); vv.y = f2tf32(vv.y);
                vv.z = f2tf32(vv.z); vv.w = f2tf32(vv.w);
                *reinterpret_cast<float4*>(&Bs[r * BS_STRIDE + q * 4]) = vv;
            }
        } else {
            constexpr int BIT = (BK * BN) / (THREADS * 4);
            constexpr int C4 = BN / 4;
#pragma unroll
            for (int t = 0; t < BIT; t++) {
                int idx = tid + t * THREADS;
                int r = idx / C4, cq = idx % C4;
                float4 vv = *reinterpret_cast<const float4*>(
                    B + (long long)(k0 + r) * ldb + n0 + cq * 4);
                vv.x = f2tf32(vv.x); vv.y = f2tf32(vv.y);
                vv.z = f2tf32(vv.z); vv.w = f2tf32(vv.w);
                *reinterpret_cast<float4*>(&Bs[r * BS_STRIDE + cq * 4]) = vv;
            }
        }
        __syncthreads();

#pragma unroll
        for (int ks = 0; ks < BK; ks += 8) {
            float4 af[MA];
            float2 bf[NA];
#pragma unroll
            for (int i = 0; i < MA; i++) {
                int r = wm + i * 16 + lr;
                af[i].x = As[r * AS_STRIDE + ks + lc];
                af[i].y = As[(r + 8) * AS_STRIDE + ks + lc];
                af[i].z = As[r * AS_STRIDE + ks + lc + 4];
                af[i].w = As[(r + 8) * AS_STRIDE + ks + lc + 4];
            }
#pragma unroll
            for (int j = 0; j < NA; j++) {
                int n = wn + j * 8 + lr;
                if (TB) {
                    bf[j].x = Bs[n * BS_STRIDE + ks + lc];
                    bf[j].y = Bs[n * BS_STRIDE + ks + lc + 4];
                } else {
                    bf[j].x = Bs[(ks + lc) * BS_STRIDE + n];
                    bf[j].y = Bs[(ks + lc + 4) * BS_STRIDE + n];
                }
            }
#pragma unroll
            for (int i = 0; i < MA; i++)
#pragma unroll
                for (int j = 0; j < NA; j++)
                    mma_tf32(acc[i][j], af[i], bf[j]);
        }
        __syncthreads();
    }

    // ---- epilogue: C = alpha*acc + beta*SRC + bias ----
#pragma unroll
    for (int i = 0; i < MA; i++) {
        int r0 = m0 + wm + i * 16 + lr;
#pragma unroll
        for (int j = 0; j < NA; j++) {
            int cc = n0 + wn + j * 8 + lc * 2;
#pragma unroll
            for (int e = 0; e < 4; e++) {
                int r = (e < 2) ? r0 : r0 + 8;
                int c = cc + (e & 1);
                long long idx = (long long)r * ldc + c;
                float v = alpha * acc[i][j][e];
                if (S) v += beta * S[idx];
                if (bias) v += bias[c];
                C[idx] = v;
            }
        }
    }
}

// Row softmax over 2048 columns, in-place. One block (256 thr) per row.
__global__ void __launch_bounds__(256) softmax2048(float* __restrict__ d) {
    __shared__ float red[8];
    const size_t base = (size_t)blockIdx.x * 2048;
    const int tid = threadIdx.x;
    float4 v0 = *reinterpret_cast<float4*>(d + base + tid * 8);
    float4 v1 = *reinterpret_cast<float4*>(d + base + tid * 8 + 4);

    float m = fmaxf(fmaxf(fmaxf(v0.x, v0.y), fmaxf(v0.z, v0.w)),
                    fmaxf(fmaxf(v1.x, v1.y), fmaxf(v1.z, v1.w)));
#pragma unroll
    for (int o = 16; o > 0; o >>= 1) m = fmaxf(m, __shfl_xor_sync(0xffffffffu, m, o));
    if ((tid & 31) == 0) red[tid >> 5] = m;
    __syncthreads();
    m = red[0];
#pragma unroll
    for (int w = 1; w < 8; w++) m = fmaxf(m, red[w]);
    __syncthreads();

    v0.x = __expf(v0.x - m); v0.y = __expf(v0.y - m);
    v0.z = __expf(v0.z - m); v0.w = __expf(v0.w - m);
    v1.x = __expf(v1.x - m); v1.y = __expf(v1.y - m);
    v1.z = __expf(v1.z - m); v1.w = __expf(v1.w - m);

    float s = v0.x + v0.y + v0.z + v0.w + v1.x + v1.y + v1.z + v1.w;
#pragma unroll
    for (int o = 16; o > 0; o >>= 1) s += __shfl_xor_sync(0xffffffffu, s, o);
    if ((tid & 31) == 0) red[tid >> 5] = s;
    __syncthreads();
    s = red[0];
#pragma unroll
    for (int w = 1; w < 8; w++) s += red[w];
    float inv = 1.0f / s;

    v0.x *= inv; v0.y *= inv; v0.z *= inv; v0.w *= inv;
    v1.x *= inv; v1.y *= inv; v1.z *= inv; v1.w *= inv;
    *reinterpret_cast<float4*>(d + base + tid * 8) = v0;
    *reinterpret_cast<float4*>(d + base + tid * 8 + 4) = v1;
}

using GemmNN = void (*)(const float*, const float*, const float*, const float*,
                        float*, int, int, int, int,
                        long long, long long, long long, long long, float, float);

extern "C" void kernel_launch(void* const* d_in, const int* in_sizes, int n_in,
                              void* d_out, int out_size) {
    const float* X  = (const float*)d_in[0];
    const float* Wq = (const float*)d_in[1];
    const float* bq = (const float*)d_in[2];
    const float* Wk = (const float*)d_in[3];
    const float* bk = (const float*)d_in[4];
    const float* Wv = (const float*)d_in[5];
    const float* bv = (const float*)d_in[6];
    const float* Wo = (const float*)d_in[7];
    const float* bo = (const float*)d_in[8];

    float *q, *k, *v, *attn, *p0, *P, *p1, *p2;
    cudaGetSymbolAddress((void**)&q, g_q);
    cudaGetSymbolAddress((void**)&k, g_k);
    cudaGetSymbolAddress((void**)&v, g_v);
    cudaGetSymbolAddress((void**)&attn, g_attn);
    cudaGetSymbolAddress((void**)&p0, g_p0);
    cudaGetSymbolAddress((void**)&P, g_P);
    cudaGetSymbolAddress((void**)&p1, g_p1);
    cudaGetSymbolAddress((void**)&p2, g_p2);

    float* out = (float*)d_out;
    const long long OUTE = (long long)N_TOK * D_EMB;              // 2,097,152
    const long long PE   = (long long)N_HEAD * N_TOK * N_TOK;     // 67,108,864
    float* pdst = ((long long)out_size >= OUTE + PE) ? out + OUTE : p2;

    const long long PS = (long long)N_TOK * N_TOK;  // per-head p stride

    dim3 blk256(256), blk128(128);

    // 1) Q/K/V = X @ W + b   [2048,1024]x[1024,1024]
    {
        dim3 g(D_EMB / 128, N_TOK / 128, 1);
        gemm_tf32_kernel<128, 128, 64, 32, false><<<g, blk256>>>(
            X, Wq, nullptr, bq, q, D_EMB, D_EMB, D_EMB, D_EMB, 0, 0, 0, 0, 1.0f, 0.0f);
        gemm_tf32_kernel<128, 128, 64, 32, false><<<g, blk256>>>(
            X, Wk, nullptr, bk, k, D_EMB, D_EMB, D_EMB, D_EMB, 0, 0, 0, 0, 1.0f, 0.0f);
        gemm_tf32_kernel<128, 128, 64, 32, false><<<g, blk256>>>(
            X, Wv, nullptr, bv, v, D_EMB, D_EMB, D_EMB, D_EMB, 0, 0, 0, 0, 1.0f, 0.0f);
    }

    // 2) scores = Q_h @ K_h^T / 8 -> p0 ; sim = K_h @ K_h^T / 32 -> P
    {
        dim3 g(N_TOK / 128, N_TOK / 128, N_HEAD);
        gemm_tf32_kernel<128, 128, 64, 32, true><<<g, blk256>>>(
            q, k, nullptr, nullptr, p0, HD, D_EMB, D_EMB, N_TOK,
            HD, HD, PS, 0, 0.125f, 0.0f);
        gemm_tf32_kernel<128, 128, 64, 32, true><<<g, blk256>>>(
            k, k, nullptr, nullptr, P, HD, D_EMB, D_EMB, N_TOK,
            HD, HD, PS, 0, 0.03125f, 0.0f);
    }

    // 3) row softmax on p0 and P
    softmax2048<<<N_HEAD * N_TOK, blk256>>>(p0);
    softmax2048<<<N_HEAD * N_TOK, blk256>>>(P);

    // 4) diffusion: p1 = 0.95*p0 + 0.05*(p0 @ P); p2 = 0.95*p0 + 0.05*(p1 @ P)
    {
        dim3 g(N_TOK / 128, N_TOK / 128, N_HEAD);
        gemm_tf32_kernel<128, 128, 64, 32, false><<<g, blk256>>>(
            p0, P, p0, nullptr, p1, N_TOK, N_TOK, N_TOK, N_TOK,
            PS, PS, PS, PS, 0.05f, 0.95f);
        gemm_tf32_kernel<128, 128, 64, 32, false><<<g, blk256>>>(
            p1, P, p0, nullptr, pdst, N_TOK, N_TOK, N_TOK, N_TOK,
            PS, PS, PS, PS, 0.05f, 0.95f);
    }

    // 5) attn_h = p_h @ V_h   [2048,2048]x[2048,64] -> attn[:, h*64:(h+1)*64]
    {
        dim3 g(1, N_TOK / 128, N_HEAD);
        gemm_tf32_kernel<128, 64, 64, 32, false><<<g, blk128>>>(
            pdst, v, nullptr, nullptr, attn, N_TOK, N_TOK, D_EMB, D_EMB,
            PS, HD, HD, 0, 1.0f, 0.0f);
    }

    // 6) out = attn @ Wo + bo
    {
        dim3 g(D_EMB / 128, N_TOK / 128, 1);
        gemm_tf32_kernel<128, 128, 64, 32, false><<<g, blk256>>>(
            attn, Wo, nullptr, bo, out, D_EMB, D_EMB, D_EMB, D_EMB,
            0, 0, 0, 0, 1.0f, 0.0f);
    }
}

// round 2
// speedup vs baseline: 1.7231x; 1.7231x over previous
#include <cuda_runtime.h>
#include <cuda_bf16.h>

// ----------------------------------------------------------------------------
// StableQGFD layer. Heavy part (2x 16-head 2048^3 diffusion GEMMs) runs in
// bf16 mma.sync with cp.async 4-stage pipeline; error-critical path stays TF32.
// ----------------------------------------------------------------------------

#define N_TOK 2048
#define D_EMB 1024
#define N_HEAD 16
#define HD 64

// Scratch (allocation-free rule: __device__ globals)
__device__ float g_q[(size_t)N_TOK * D_EMB];
__device__ float g_k[(size_t)N_TOK * D_EMB];
__device__ float g_v[(size_t)N_TOK * D_EMB];
__device__ float g_attn[(size_t)N_TOK * D_EMB];
__device__ float g_p0 [(size_t)N_HEAD * N_TOK * N_TOK];   // p0 fp32
__device__ float g_sim[(size_t)N_HEAD * N_TOK * N_TOK];   // raw KK^T logits
__device__ __nv_bfloat16 g_h1[(size_t)N_HEAD * N_TOK * N_TOK]; // P bf16 (row) -> p1 bf16
__device__ __nv_bfloat16 g_h2[(size_t)N_HEAD * N_TOK * N_TOK]; // P^T bf16
__device__ __nv_bfloat16 g_h3[(size_t)N_HEAD * N_TOK * N_TOK]; // p0 bf16

__device__ __forceinline__ float f2tf32(float x) {
    asm("cvt.rna.tf32.f32 %0, %0;" : "+f"(x));
    return x;
}

__device__ __forceinline__ void mma_tf32(float* c, const float4& a, const float2& b) {
    unsigned a0 = __float_as_uint(a.x), a1 = __float_as_uint(a.y);
    unsigned a2 = __float_as_uint(a.z), a3 = __float_as_uint(a.w);
    unsigned b0 = __float_as_uint(b.x), b1 = __float_as_uint(b.y);
    asm volatile(
        "mma.sync.aligned.m16n8k8.row.col.f32.tf32.tf32.f32 "
        "{%0,%1,%2,%3},{%4,%5,%6,%7},{%8,%9},{%0,%1,%2,%3};"
        : "+f"(c[0]), "+f"(c[1]), "+f"(c[2]), "+f"(c[3])
        : "r"(a0), "r"(a1), "r"(a2), "r"(a3), "r"(b0), "r"(b1));
}

// ======================= TF32 general GEMM (round-1) ========================
template <int BM, int BN, int WM, int WN, bool TB>
__global__ void __launch_bounds__((BM / WM) * (BN / WN) * 32, 2)
gemm_tf32_kernel(const float* __restrict__ A, const float* __restrict__ B,
                 const float* __restrict__ SRC, const float* __restrict__ bias,
                 float* __restrict__ C,
                 int K, int lda, int ldb, int ldc,
                 long long sA, long long sB, long long sC, long long sS,
                 float alpha, float beta) {
    constexpr int BK = 16;
    constexpr int THREADS = (BM / WM) * (BN / WN) * 32;
    constexpr int MA = WM / 16;
    constexpr int NA = WN / 8;
    constexpr int AS_STRIDE = BK + 4;
    constexpr int BS_ROWS   = TB ? BN : BK;
    constexpr int BS_STRIDE = TB ? (BK + 4) : (BN + 8);

    __shared__ float As[BM * AS_STRIDE];
    __shared__ float Bs[BS_ROWS * BS_STRIDE];

    const int z = blockIdx.z;
    A += (long long)z * sA;
    B += (long long)z * sB;
    C += (long long)z * sC;
    const float* S = SRC ? SRC + (long long)z * sS : nullptr;

    const int m0 = blockIdx.y * BM;
    const int n0 = blockIdx.x * BN;
    const int tid = threadIdx.x;
    const int lane = tid & 31, warp = tid >> 5;
    constexpr int WARPS_N = BN / WN;
    const int wm = (warp / WARPS_N) * WM;
    const int wn = (warp % WARPS_N) * WN;
    const int lr = lane >> 2;
    const int lc = lane & 3;

    float acc[MA][NA][4];
#pragma unroll
    for (int i = 0; i < MA; i++)
#pragma unroll
        for (int j = 0; j < NA; j++) {
            acc[i][j][0] = 0.f; acc[i][j][1] = 0.f;
            acc[i][j][2] = 0.f; acc[i][j][3] = 0.f;
        }

    for (int k0 = 0; k0 < K; k0 += BK) {
        constexpr int AIT = (BM * BK) / (THREADS * 4);
#pragma unroll
        for (int t = 0; t < AIT; t++) {
            int idx = tid + t * THREADS;
            int r = idx >> 2, q = idx & 3;
            float4 vv = *reinterpret_cast<const float4*>(
                A + (long long)(m0 + r) * lda + k0 + q * 4);
            vv.x = f2tf32(vv.x); vv.y = f2tf32(vv.y);
            vv.z = f2tf32(vv.z); vv.w = f2tf32(vv.w);
            *reinterpret_cast<float4*>(&As[r * AS_STRIDE + q * 4]) = vv;
        }
        if (TB) {
            constexpr int BIT = (BN * BK) / (THREADS * 4);
#pragma unroll
            for (int t = 0; t < BIT; t++) {
                int idx = tid + t * THREADS;
                int r = idx >> 2, q = idx & 3;
                float4 vv = *reinterpret_cast<const float4*>(
                    B + (long long)(n0 + r) * ldb + k0 + q * 4);
                vv.x = f2tf32(vv.x); vv.y = f2tf32(vv.y);
                vv.z = f2tf32(vv.z); vv.w = f2tf32(vv.w);
                *reinterpret_cast<float4*>(&Bs[r * BS_STRIDE + q * 4]) = vv;
            }
        } else {
            constexpr int BIT = (BK * BN) / (THREADS * 4);
            constexpr int C4 = BN / 4;
#pragma unroll
            for (int t = 0; t < BIT; t++) {
                int idx = tid + t * THREADS;
                int r = idx / C4, cq = idx % C4;
                float4 vv = *reinterpret_cast<const float4*>(
                    B + (long long)(k0 + r) * ldb + n0 + cq * 4);
                vv.x = f2tf32(vv.x); vv.y = f2tf32(vv.y);
                vv.z = f2tf32(vv.z); vv.w = f2tf32(vv.w);
                *reinterpret_cast<float4*>(&Bs[r * BS_STRIDE + cq * 4]) = vv;
            }
        }
        __syncthreads();

#pragma unroll
        for (int ks = 0; ks < BK; ks += 8) {
            float4 af[MA];
            float2 bf[NA];
#pragma unroll
            for (int i = 0; i < MA; i++) {
                int r = wm + i * 16 + lr;
                af[i].x = As[r * AS_STRIDE + ks + lc];
                af[i].y = As[(r + 8) * AS_STRIDE + ks + lc];
                af[i].z = As[r * AS_STRIDE + ks + lc + 4];
                af[i].w = As[(r + 8) * AS_STRIDE + ks + lc + 4];
            }
#pragma unroll
            for (int j = 0; j < NA; j++) {
                int n = wn + j * 8 + lr;
                if (TB) {
                    bf[j].x = Bs[n * BS_STRIDE + ks + lc];
                    bf[j].y = Bs[n * BS_STRIDE + ks + lc + 4];
                } else {
                    bf[j].x = Bs[(ks + lc) * BS_STRIDE + n];
                    bf[j].y = Bs[(ks + lc + 4) * BS_STRIDE + n];
                }
            }
#pragma unroll
            for (int i = 0; i < MA; i++)
#pragma unroll
                for (int j = 0; j < NA; j++)
                    mma_tf32(acc[i][j], af[i], bf[j]);
        }
        __syncthreads();
    }

#pragma unroll
    for (int i = 0; i < MA; i++) {
        int r0 = m0 + wm + i * 16 + lr;
#pragma unroll
        for (int j = 0; j < NA; j++) {
            int cc = n0 + wn + j * 8 + lc * 2;
#pragma unroll
            for (int e = 0; e < 4; e++) {
                int r = (e < 2) ? r0 : r0 + 8;
                int c = cc + (e & 1);
                long long idx = (long long)r * ldc + c;
                float v = alpha * acc[i][j][e];
                if (S) v += beta * S[idx];
                if (bias) v += bias[c];
                C[idx] = v;
            }
        }
    }
}

// ======================= bf16 diffusion GEMM ================================
// C = 0.95*SRC + 0.05 * A @ Bt^T, per-head (blockIdx.z). A, Bt bf16 row-major
// [2048,2048]; SRC fp32. WRITE_BF16 selects bf16 vs fp32 output.
#define DBM 128
#define DBN 256
#define DBK 32
#define DSTAGES 4
#define DTHREADS 256
#define DSTRIDE 40   // BK + 8 bf16 pad -> 80B row stride (conflict-free, 16B-mult)
#define DSMEM_DYN ((DBM + DBN) * DSTRIDE * 2 * DSTAGES)

__device__ __forceinline__ void cpa16(__nv_bfloat16* dst, const __nv_bfloat16* src) {
    unsigned d = (unsigned)__cvta_generic_to_shared(dst);
    asm volatile("cp.async.cg.shared.global [%0], [%1], 16;" :: "r"(d), "l"(src));
}

template <bool WRITE_BF16>
__global__ void __launch_bounds__(DTHREADS, 1)
diffuse_gemm_bf16(const __nv_bfloat16* __restrict__ A,
                  const __nv_bfloat16* __restrict__ Bt,
                  const float* __restrict__ SRC,
                  float* __restrict__ Cf,
                  __nv_bfloat16* __restrict__ Ch) {
    constexpr int LD = 2048;
    constexpr long long PS = (long long)2048 * 2048;
    extern __shared__ __nv_bfloat16 sm[];

    const int z = blockIdx.z;
    A += z * PS; Bt += z * PS; SRC += z * PS;
    if constexpr (WRITE_BF16) Ch += z * PS; else Cf += z * PS;

    const int m0 = blockIdx.y * DBM, n0 = blockIdx.x * DBN;
    const int tid = threadIdx.x, lane = tid & 31, warp = tid >> 5;
    const int wm = (warp >> 2) * 64, wn = (warp & 3) * 64;
    const int lr = lane >> 2, lc = lane & 3;

#define AS_(s) (sm + (s) * (DBM + DBN) * DSTRIDE)
#define BS_(s) (sm + (s) * (DBM + DBN) * DSTRIDE + DBM * DSTRIDE)

    auto load_stage = [&](int s, int k0) {
        __nv_bfloat16* as = AS_(s);
#pragma unroll
        for (int t = 0; t < 2; t++) {
            int idx = tid + t * DTHREADS;
            int r = idx >> 2, ch = idx & 3;
            cpa16(as + r * DSTRIDE + ch * 8, A + (long long)(m0 + r) * LD + k0 + ch * 8);
        }
        __nv_bfloat16* bs = BS_(s);
#pragma unroll
        for (int t = 0; t < 4; t++) {
            int idx = tid + t * DTHREADS;
            int r = idx >> 2, ch = idx & 3;
            cpa16(bs + r * DSTRIDE + ch * 8, Bt + (long long)(n0 + r) * LD + k0 + ch * 8);
        }
        asm volatile("cp.async.commit_group;");
    };

    float acc[4][8][4] = {};

    constexpr int NIT = 2048 / DBK;  // 64
    for (int p = 0; p < DSTAGES - 1; p++) load_stage(p, p * DBK);

    for (int i = 0; i < NIT; i++) {
        if (i + DSTAGES - 1 < NIT) {
            asm volatile("cp.async.wait_group 2;");
            __syncthreads();
            load_stage((i + DSTAGES - 1) % DSTAGES, (i + DSTAGES - 1) * DBK);
        } else {
            asm volatile("cp.async.wait_group 0;");
            __syncthreads();
        }
        const __nv_bfloat16* as = AS_(i % DSTAGES);
        const __nv_bfloat16* bs = BS_(i % DSTAGES);
#pragma unroll
        for (int ks = 0; ks < DBK; ks += 16) {
            unsigned af[4][4], bf[8][2];
#pragma unroll
            for (int ii = 0; ii < 4; ii++) {
                const __nv_bfloat16* b0 = as + (wm + ii * 16 + lr) * DSTRIDE + ks + 2 * lc;
                af[ii][0] = *(const unsigned*)(b0);
                af[ii][1] = *(const unsigned*)(b0 + 8 * DSTRIDE);
                af[ii][2] = *(const unsigned*)(b0 + 8);
                af[ii][3] = *(const unsigned*)(b0 + 8 * DSTRIDE + 8);
            }
#pragma unroll
            for (int j = 0; j < 8; j++) {
                const __nv_bfloat16* b0 = bs + (wn + j * 8 + lr) * DSTRIDE + ks + 2 * lc;
                bf[j][0] = *(const unsigned*)(b0);
                bf[j][1] = *(const unsigned*)(b0 + 8);
            }
#pragma unroll
            for (int ii = 0; ii < 4; ii++)
#pragma unroll
                for (int j = 0; j < 8; j++)
                    asm volatile(
                        "mma.sync.aligned.m16n8k16.row.col.f32.bf16.bf16.f32 "
                        "{%0,%1,%2,%3},{%4,%5,%6,%7},{%8,%9},{%0,%1,%2,%3};"
                        : "+f"(acc[ii][j][0]), "+f"(acc[ii][j][1]),
                          "+f"(acc[ii][j][2]), "+f"(acc[ii][j][3])
                        : "r"(af[ii][0]), "r"(af[ii][1]), "r"(af[ii][2]), "r"(af[ii][3]),
                          "r"(bf[j][0]), "r"(bf[j][1]));
        }
    }

#pragma unroll
    for (int ii = 0; ii < 4; ii++) {
        int r0 = m0 + wm + ii * 16 + lr;
#pragma unroll
        for (int j = 0; j < 8; j++) {
            int c0 = n0 + wn + j * 8 + 2 * lc;
            long long i0 = (long long)r0 * LD + c0;
            long long i1 = i0 + 8LL * LD;
            float2 s0 = *(const float2*)(SRC + i0);
            float2 s1 = *(const float2*)(SRC + i1);
            float o0 = 0.95f * s0.x + 0.05f * acc[ii][j][0];
            float o1 = 0.95f * s0.y + 0.05f * acc[ii][j][1];
            float o2 = 0.95f * s1.x + 0.05f * acc[ii][j][2];
            float o3 = 0.95f * s1.y + 0.05f * acc[ii][j][3];
            if constexpr (WRITE_BF16) {
                *(__nv_bfloat162*)(Ch + i0) = __floats2bfloat162_rn(o0, o1);
                *(__nv_bfloat162*)(Ch + i1) = __floats2bfloat162_rn(o2, o3);
            } else {
                *(float2*)(Cf + i0) = make_float2(o0, o1);
                *(float2*)(Cf + i1) = make_float2(o2, o3);
            }
        }
    }
#undef AS_
#undef BS_
}

// ======================= softmax variants ===================================
// Row softmax over 2048 cols. fp32 in-place + bf16 row-major copy.
__global__ void __launch_bounds__(256) softmax2048_fh(float* __restrict__ d,
                                                      __nv_bfloat16* __restrict__ h) {
    __shared__ float red[8];
    const size_t base = (size_t)blockIdx.x * 2048;
    const int tid = threadIdx.x;
    float4 v0 = *reinterpret_cast<float4*>(d + base + tid * 8);
    float4 v1 = *reinterpret_cast<float4*>(d + base + tid * 8 + 4);

    float m = fmaxf(fmaxf(fmaxf(v0.x, v0.y), fmaxf(v0.z, v0.w)),
                    fmaxf(fmaxf(v1.x, v1.y), fmaxf(v1.z, v1.w)));
#pragma unroll
    for (int o = 16; o > 0; o >>= 1) m = fmaxf(m, __shfl_xor_sync(0xffffffffu, m, o));
    if ((tid & 31) == 0) red[tid >> 5] = m;
    __syncthreads();
    m = red[0];
#pragma unroll
    for (int w = 1; w < 8; w++) m = fmaxf(m, red[w]);
    __syncthreads();

    v0.x = __expf(v0.x - m); v0.y = __expf(v0.y - m);
    v0.z = __expf(v0.z - m); v0.w = __expf(v0.w - m);
    v1.x = __expf(v1.x - m); v1.y = __expf(v1.y - m);
    v1.z = __expf(v1.z - m); v1.w = __expf(v1.w - m);

    float s = v0.x + v0.y + v0.z + v0.w + v1.x + v1.y + v1.z + v1.w;
#pragma unroll
    for (int o = 16; o > 0; o >>= 1) s += __shfl_xor_sync(0xffffffffu, s, o);
    if ((tid & 31) == 0) red[tid >> 5] = s;
    __syncthreads();
    s = red[0];
#pragma unroll
    for (int w = 1; w < 8; w++) s += red[w];
    float inv = 1.0f / s;

    v0.x *= inv; v0.y *= inv; v0.z *= inv; v0.w *= inv;
    v1.x *= inv; v1.y *= inv; v1.z *= inv; v1.w *= inv;
    *reinterpret_cast<float4*>(d + base + tid * 8) = v0;
    *reinterpret_cast<float4*>(d + base + tid * 8 + 4) = v1;

    __nv_bfloat162* hp = reinterpret_cast<__nv_bfloat162*>(h + base) + tid * 4;
    hp[0] = __floats2bfloat162_rn(v0.x, v0.y);
    hp[1] = __floats2bfloat162_rn(v0.z, v0.w);
    hp[2] = __floats2bfloat162_rn(v1.x, v1.y);
    hp[3] = __floats2bfloat162_rn(v1.z, v1.w);
}

// Row softmax, bf16-only output (fp32 input untouched / dead after).
__global__ void __launch_bounds__(256) softmax2048_h(const float* __restrict__ d,
                                                     __nv_bfloat16* __restrict__ h) {
    __shared__ float red[8];
    const size_t base = (size_t)blockIdx.x * 2048;
    const int tid = threadIdx.x;
    float4 v0 = *reinterpret_cast<const float4*>(d + base + tid * 8);
    float4 v1 = *reinterpret_cast<const float4*>(d + base + tid * 8 + 4);

    float m = fmaxf(fmaxf(fmaxf(v0.x, v0.y), fmaxf(v0.z, v0.w)),
                    fmaxf(fmaxf(v1.x, v1.y), fmaxf(v1.z, v1.w)));
#pragma unroll
    for (int o = 16; o > 0; o >>= 1) m = fmaxf(m, __shfl_xor_sync(0xffffffffu, m, o));
    if ((tid & 31) == 0) red[tid >> 5] = m;
    __syncthreads();
    m = red[0];
#pragma unroll
    for (int w = 1; w < 8; w++) m = fmaxf(m, red[w]);
    __syncthreads();

    v0.x = __expf(v0.x - m); v0.y = __expf(v0.y - m);
    v0.z = __expf(v0.z - m); v0.w = __expf(v0.w - m);
    v1.x = __expf(v1.x - m); v1.y = __expf(v1.y - m);
    v1.z = __expf(v1.z - m); v1.w = __expf(v1.w - m);

    float s = v0.x + v0.y + v0.z + v0.w + v1.x + v1.y + v1.z + v1.w;
#pragma unroll
    for (int o = 16; o > 0; o >>= 1) s += __shfl_xor_sync(0xffffffffu, s, o);
    if ((tid & 31) == 0) red[tid >> 5] = s;
    __syncthreads();
    s = red[0];
#pragma unroll
    for (int w = 1; w < 8; w++) s += red[w];
    float inv = 1.0f / s;

    __nv_bfloat162* hp = reinterpret_cast<__nv_bfloat162*>(h + base) + tid * 4;
    hp[0] = __floats2bfloat162_rn(v0.x * inv, v0.y * inv);
    hp[1] = __floats2bfloat162_rn(v0.z * inv, v0.w * inv);
    hp[2] = __floats2bfloat162_rn(v1.x * inv, v1.y * inv);
    hp[3] = __floats2bfloat162_rn(v1.z * inv, v1.w * inv);
}

// 32x32 tiled bf16 transpose, per head (blockIdx.z).
__global__ void __launch_bounds__(256) transpose_bf16(const __nv_bfloat16* __restrict__ in,
                                                      __nv_bfloat16* __restrict__ out) {
    __shared__ __nv_bfloat16 t[32][33];
    const size_t base = (size_t)blockIdx.z * 2048 * 2048;
    const int x0 = blockIdx.x * 32, y0 = blockIdx.y * 32;
    const int tx = threadIdx.x & 31, ty = threadIdx.x >> 5;  // 32x8
#pragma unroll
    for (int r = 0; r < 32; r += 8)
        t[ty + r][tx] = in[base + (size_t)(y0 + ty + r) * 2048 + x0 + tx];
    __syncthreads();
#pragma unroll
    for (int r = 0; r < 32; r += 8)
        out[base + (size_t)(x0 + ty + r) * 2048 + y0 + tx] = t[tx][ty + r];
}

// ======================= host launcher ======================================
extern "C" void kernel_launch(void* const* d_in, const int* in_sizes, int n_in,
                              void* d_out, int out_size) {
    const float* X  = (const float*)d_in[0];
    const float* Wq = (const float*)d_in[1];
    const float* bq = (const float*)d_in[2];
    const float* Wk = (const float*)d_in[3];
    const float* bk = (const float*)d_in[4];
    const float* Wv = (const float*)d_in[5];
    const float* bv = (const float*)d_in[6];
    const float* Wo = (const float*)d_in[7];
    const float* bo = (const float*)d_in[8];

    float *q, *k, *v, *attn, *p0, *sim;
    __nv_bfloat16 *h1, *h2, *h3;
    cudaGetSymbolAddress((void**)&q, g_q);
    cudaGetSymbolAddress((void**)&k, g_k);
    cudaGetSymbolAddress((void**)&v, g_v);
    cudaGetSymbolAddress((void**)&attn, g_attn);
    cudaGetSymbolAddress((void**)&p0, g_p0);
    cudaGetSymbolAddress((void**)&sim, g_sim);
    cudaGetSymbolAddress((void**)&h1, g_h1);
    cudaGetSymbolAddress((void**)&h2, g_h2);
    cudaGetSymbolAddress((void**)&h3, g_h3);

    float* out = (float*)d_out;
    const long long OUTE = (long long)N_TOK * D_EMB;
    const long long PE   = (long long)N_HEAD * N_TOK * N_TOK;
    float* pdst = ((long long)out_size >= OUTE + PE) ? out + OUTE : p0;  // p output
    const long long PS = (long long)N_TOK * N_TOK;

    dim3 blk256(256), blk128(128);

    // 1) Q/K/V projections (TF32)
    {
        dim3 g(D_EMB / 128, N_TOK / 128, 1);
        gemm_tf32_kernel<128, 128, 64, 32, false><<<g, blk256>>>(
            X, Wq, nullptr, bq, q, D_EMB, D_EMB, D_EMB, D_EMB, 0, 0, 0, 0, 1.0f, 0.0f);
        gemm_tf32_kernel<128, 128, 64, 32, false><<<g, blk256>>>(
            X, Wk, nullptr, bk, k, D_EMB, D_EMB, D_EMB, D_EMB, 0, 0, 0, 0, 1.0f, 0.0f);
        gemm_tf32_kernel<128, 128, 64, 32, false><<<g, blk256>>>(
            X, Wv, nullptr, bv, v, D_EMB, D_EMB, D_EMB, D_EMB, 0, 0, 0, 0, 1.0f, 0.0f);
    }

    // 2) scores -> p0 logits ; KK^T -> sim logits (TF32, NT)
    {
        dim3 g(N_TOK / 128, N_TOK / 128, N_HEAD);
        gemm_tf32_kernel<128, 128, 64, 32, true><<<g, blk256>>>(
            q, k, nullptr, nullptr, p0, HD, D_EMB, D_EMB, N_TOK,
            HD, HD, PS, 0, 0.125f, 0.0f);
        gemm_tf32_kernel<128, 128, 64, 32, true><<<g, blk256>>>(
            k, k, nullptr, nullptr, sim, HD, D_EMB, D_EMB, N_TOK,
            HD, HD, PS, 0, 0.03125f, 0.0f);
    }

    // 3) softmaxes: p0 (fp32 in-place + bf16 copy h3); P (bf16 h1 only)
    softmax2048_fh<<<N_HEAD * N_TOK, blk256>>>(p0, h3);
    softmax2048_h <<<N_HEAD * N_TOK, blk256>>>(sim, h1);

    // 4) transpose P bf16 -> Pt (h2)
    transpose_bf16<<<dim3(64, 64, N_HEAD), blk256>>>(h1, h2);

    // 5) diffusion (bf16 MMA): p1(bf16,h1) = .95 p0 + .05 p0h @ Pt^T
    //                          p2(fp32)    = .95 p0 + .05 p1h @ Pt^T
    {
        cudaFuncSetAttribute(diffuse_gemm_bf16<true>,
                             cudaFuncAttributeMaxDynamicSharedMemorySize, DSMEM_DYN);
        cudaFuncSetAttribute(diffuse_gemm_bf16<false>,
                             cudaFuncAttributeMaxDynamicSharedMemorySize, DSMEM_DYN);
        dim3 g(N_TOK / DBN, N_TOK / DBM, N_HEAD);
        diffuse_gemm_bf16<true><<<g, DTHREADS, DSMEM_DYN>>>(h3, h2, p0, nullptr, h1);
        diffuse_gemm_bf16<false><<<g, DTHREADS, DSMEM_DYN>>>(h1, h2, p0, pdst, nullptr);
    }

    // 6) attn_h = p_h @ V_h (TF32)
    {
        dim3 g(1, N_TOK / 128, N_HEAD);
        gemm_tf32_kernel<128, 64, 64, 32, false><<<g, blk128>>>(
            pdst, v, nullptr, nullptr, attn, N_TOK, N_TOK, D_EMB, D_EMB,
            PS, HD, HD, 0, 1.0f, 0.0f);
    }

    // 7) out = attn @ Wo + bo (TF32)
    {
        dim3 g(D_EMB / 128, N_TOK / 128, 1);
        gemm_tf32_kernel<128, 128, 64, 32, false><<<g, blk256>>>(
            attn, Wo, nullptr, bo, out, D_EMB, D_EMB, D_EMB, D_EMB,
            0, 0, 0, 0, 1.0f, 0.0f);
    }
}

// round 4
// speedup vs baseline: 1.8693x; 1.0848x over previous
#include <cuda_runtime.h>
#include <cuda_bf16.h>
#include <cstdint>

// ----------------------------------------------------------------------------
// StableQGFD layer. Diffusion (2x 16-head 2048^3 GEMMs, 93% of FLOPs) runs on
// legacy mma.sync FP8 (e4m3, scale 256) — tcgen05 is blocked by the harness's
// compute_103 PTX target. Error-critical path stays TF32/fp32. Small kernels
// overlap via stream fork/join (graph-capturable event pattern).
// ----------------------------------------------------------------------------

#define N_TOK 2048
#define D_EMB 1024
#define N_HEAD 16
#define HD 64

// Scratch (allocation-free rule: __device__ globals)
__device__ float g_q[(size_t)N_TOK * D_EMB];
__device__ float g_k[(size_t)N_TOK * D_EMB];
__device__ float g_v[(size_t)N_TOK * D_EMB];
__device__ float g_attn[(size_t)N_TOK * D_EMB];
__device__ float g_p0 [(size_t)N_HEAD * N_TOK * N_TOK];   // p0 fp32 (softmax'd)
__device__ float g_sim[(size_t)N_HEAD * N_TOK * N_TOK];   // raw KK^T logits
__device__ uint8_t g_a8 [(size_t)N_HEAD * N_TOK * N_TOK]; // p0  e4m3 x256
__device__ uint8_t g_b8 [(size_t)N_HEAD * N_TOK * N_TOK]; // P   e4m3 x256 (rows)
__device__ uint8_t g_bt8[(size_t)N_HEAD * N_TOK * N_TOK]; // P^T e4m3 x256
__device__ uint8_t g_c8 [(size_t)N_HEAD * N_TOK * N_TOK]; // p1  e4m3 x256

__device__ __forceinline__ float f2tf32(float x) {
    asm("cvt.rna.tf32.f32 %0, %0;" : "+f"(x));
    return x;
}

// pack two floats to e4m3x2: hi -> upper byte, lo -> lower byte
__device__ __forceinline__ unsigned short f8pack2(float lo, float hi) {
    unsigned short r;
    asm("cvt.rn.satfinite.e4m3x2.f32 %0, %1, %2;" : "=h"(r) : "f"(hi), "f"(lo));
    return r;
}

__device__ __forceinline__ void mma_tf32(float* c, const float4& a, const float2& b) {
    unsigned a0 = __float_as_uint(a.x), a1 = __float_as_uint(a.y);
    unsigned a2 = __float_as_uint(a.z), a3 = __float_as_uint(a.w);
    unsigned b0 = __float_as_uint(b.x), b1 = __float_as_uint(b.y);
    asm volatile(
        "mma.sync.aligned.m16n8k8.row.col.f32.tf32.tf32.f32 "
        "{%0,%1,%2,%3},{%4,%5,%6,%7},{%8,%9},{%0,%1,%2,%3};"
        : "+f"(c[0]), "+f"(c[1]), "+f"(c[2]), "+f"(c[3])
        : "r"(a0), "r"(a1), "r"(a2), "r"(a3), "r"(b0), "r"(b1));
}

__device__ __forceinline__ void mma_e4m3(float* c, const unsigned* a, const unsigned* b) {
    asm volatile(
        "mma.sync.aligned.m16n8k32.row.col.f32.e4m3.e4m3.f32 "
        "{%0,%1,%2,%3},{%4,%5,%6,%7},{%8,%9},{%0,%1,%2,%3};"
        : "+f"(c[0]), "+f"(c[1]), "+f"(c[2]), "+f"(c[3])
        : "r"(a[0]), "r"(a[1]), "r"(a[2]), "r"(a[3]), "r"(b[0]), "r"(b[1]));
}

// ======================= FP8 diffusion GEMM =================================
// C = 0.95*SRC + (0.05/65536) * A8 @ Bt8^T per head (blockIdx.z).
// A8, Bt8: e4m3 (value x256) row-major [2048,2048], K contiguous.
// W8: write p1 as e4m3 x256; else fp32.
#define FBM 128
#define FBN 256
#define FBK 64
#define FST 4
#define FROW 80                                  // 64B data + 16B pad
#define FSTAGE_BYTES ((FBM + FBN) * FROW)        // 30720
#define FSMEM (FST * FSTAGE_BYTES)               // 122880
#define FNIT (N_TOK / FBK)                       // 32

template <bool W8>
__global__ void __launch_bounds__(256, 1)
f8_diffuse(const uint8_t* __restrict__ A, const uint8_t* __restrict__ Bt,
           const float* __restrict__ SRC,
           float* __restrict__ Cf, uint8_t* __restrict__ C8)
{
    extern __shared__ __align__(128) uint8_t sm[];
    constexpr long long PS = (long long)N_TOK * N_TOK;
    const int z = blockIdx.z;
    A += z * PS; Bt += z * PS; SRC += z * PS;
    if constexpr (W8) C8 += z * PS; else Cf += z * PS;

    const int m0 = blockIdx.y * FBM, n0 = blockIdx.x * FBN;
    const int tid = threadIdx.x, lane = tid & 31, warp = tid >> 5;
    const int wm = (warp >> 2) * 64, wn = (warp & 3) * 64;
    const int lr = lane >> 2, lc = lane & 3;

    auto load_stage = [&](int s, int kc) {
        uint8_t* base = sm + s * FSTAGE_BYTES;
        const int ke = kc * FBK;
#pragma unroll
        for (int t = 0; t < 2; t++) {                 // A: 128 rows x 64B
            int idx = tid + t * 256;
            int r = idx >> 2, c = idx & 3;
            unsigned dst = (unsigned)__cvta_generic_to_shared(base + r * FROW + c * 16);
            const uint8_t* src = A + (long long)(m0 + r) * N_TOK + ke + c * 16;
            asm volatile("cp.async.cg.shared.global [%0], [%1], 16;" :: "r"(dst), "l"(src));
        }
        uint8_t* bbase = base + FBM * FROW;
#pragma unroll
        for (int t = 0; t < 4; t++) {                 // B: 256 rows x 64B
            int idx = tid + t * 256;
            int r = idx >> 2, c = idx & 3;
            unsigned dst = (unsigned)__cvta_generic_to_shared(bbase + r * FROW + c * 16);
            const uint8_t* src = Bt + (long long)(n0 + r) * N_TOK + ke + c * 16;
            asm volatile("cp.async.cg.shared.global [%0], [%1], 16;" :: "r"(dst), "l"(src));
        }
        asm volatile("cp.async.commit_group;");
    };

    float acc[4][8][4] = {};

    for (int p = 0; p < FST - 1; p++) load_stage(p, p);

    for (int i = 0; i < FNIT; i++) {
        if (i + FST - 1 < FNIT) {
            asm volatile("cp.async.wait_group 2;");
            __syncthreads();
            load_stage((i + FST - 1) % FST, i + FST - 1);
        } else {
            asm volatile("cp.async.wait_group 0;");
            __syncthreads();
        }
        const uint8_t* as = sm + (i % FST) * FSTAGE_BYTES;
        const uint8_t* bs = as + FBM * FROW;
#pragma unroll
        for (int ks = 0; ks < FBK; ks += 32) {
            unsigned af[4][4], bf[8][2];
#pragma unroll
            for (int ii = 0; ii < 4; ii++) {
                const uint8_t* p0 = as + (wm + ii * 16 + lr) * FROW + ks + lc * 4;
                af[ii][0] = *(const unsigned*)(p0);
                af[ii][1] = *(const unsigned*)(p0 + 8 * FROW);
                af[ii][2] = *(const unsigned*)(p0 + 16);
                af[ii][3] = *(const unsigned*)(p0 + 8 * FROW + 16);
            }
#pragma unroll
            for (int j = 0; j < 8; j++) {
                const uint8_t* p0 = bs + (wn + j * 8 + lr) * FROW + ks + lc * 4;
                bf[j][0] = *(const unsigned*)(p0);
                bf[j][1] = *(const unsigned*)(p0 + 16);
            }
#pragma unroll
            for (int ii = 0; ii < 4; ii++)
#pragma unroll
                for (int j = 0; j < 8; j++)
                    mma_e4m3(acc[ii][j], af[ii], bf[j]);
        }
    }

    // epilogue. acc = 65536 * (p_prev @ P). true term = acc/65536.
#pragma unroll
    for (int ii = 0; ii < 4; ii++) {
        int r0 = m0 + wm + ii * 16 + lr;
#pragma unroll
        for (int j = 0; j < 8; j++) {
            int c0 = n0 + wn + j * 8 + 2 * lc;
            long long i0 = (long long)r0 * N_TOK + c0;
            long long i1 = i0 + 8LL * N_TOK;
            float2 s0 = *(const float2*)(SRC + i0);
            float2 s1 = *(const float2*)(SRC + i1);
            if constexpr (W8) {
                // store 256*p1 = 243.2*p0 + (0.05*256/65536)*acc
                float t0 = 243.2f * s0.x + 1.953125e-4f * acc[ii][j][0];
                float t1 = 243.2f * s0.y + 1.953125e-4f * acc[ii][j][1];
                float t2 = 243.2f * s1.x + 1.953125e-4f * acc[ii][j][2];
                float t3 = 243.2f * s1.y + 1.953125e-4f * acc[ii][j][3];
                *(unsigned short*)(C8 + i0) = f8pack2(t0, t1);
                *(unsigned short*)(C8 + i1) = f8pack2(t2, t3);
            } else {
                constexpr float AEF = 0.05f / 65536.0f;
                float2 o0, o1;
                o0.x = 0.95f * s0.x + AEF * acc[ii][j][0];
                o0.y = 0.95f * s0.y + AEF * acc[ii][j][1];
                o1.x = 0.95f * s1.x + AEF * acc[ii][j][2];
                o1.y = 0.95f * s1.y + AEF * acc[ii][j][3];
                *(float2*)(Cf + i0) = o0;
                *(float2*)(Cf + i1) = o1;
            }
        }
    }
}

// ======================= TF32 general GEMM ==================================
template <int BM, int BN, int WM, int WN, bool TB>
__global__ void __launch_bounds__((BM / WM) * (BN / WN) * 32, 2)
gemm_tf32_kernel(const float* __restrict__ A, const float* __restrict__ B,
                 const float* __restrict__ SRC, const float* __restrict__ bias,
                 float* __restrict__ C,
                 int K, int lda, int ldb, int ldc,
                 long long sA, long long sB, long long sC, long long sS,
                 float alpha, float beta) {
    constexpr int BK = 16;
    constexpr int THREADS = (BM / WM) * (BN / WN) * 32;
    constexpr int MA = WM / 16;
    constexpr int NA = WN / 8;
    constexpr int AS_STRIDE = BK + 4;
    constexpr int BS_ROWS   = TB ? BN : BK;
    constexpr int BS_STRIDE = TB ? (BK + 4) : (BN + 8);

    __shared__ float As[BM * AS_STRIDE];
    __shared__ float Bs[BS_ROWS * BS_STRIDE];

    const int z = blockIdx.z;
    A += (long long)z * sA;
    B += (long long)z * sB;
    C += (long long)z * sC;
    const float* S = SRC ? SRC + (long long)z * sS : nullptr;

    const int m0 = blockIdx.y * BM;
    const int n0 = blockIdx.x * BN;
    const int tid = threadIdx.x;
    const int lane = tid & 31, warp = tid >> 5;
    constexpr int WARPS_N = BN / WN;
    const int wm = (warp / WARPS_N) * WM;
    const int wn = (warp % WARPS_N) * WN;
    const int lr = lane >> 2;
    const int lc = lane & 3;

    float acc[MA][NA][4];
#pragma unroll
    for (int i = 0; i < MA; i++)
#pragma unroll
        for (int j = 0; j < NA; j++) {
            acc[i][j][0] = 0.f; acc[i][j][1] = 0.f;
            acc[i][j][2] = 0.f; acc[i][j][3] = 0.f;
        }

    for (int k0 = 0; k0 < K; k0 += BK) {
        constexpr int AIT = (BM * BK) / (THREADS * 4);
#pragma unroll
        for (int t = 0; t < AIT; t++) {
            int idx = tid + t * THREADS;
            int r = idx >> 2, q = idx & 3;
            float4 vv = *reinterpret_cast<const float4*>(
                A + (long long)(m0 + r) * lda + k0 + q * 4);
            vv.x = f2tf32(vv.x); vv.y = f2tf32(vv.y);
            vv.z = f2tf32(vv.z); vv.w = f2tf32(vv.w);
            *reinterpret_cast<float4*>(&As[r * AS_STRIDE + q * 4]) = vv;
        }
        if (TB) {
            constexpr int BIT = (BN * BK) / (THREADS * 4);
#pragma unroll
            for (int t = 0; t < BIT; t++) {
                int idx = tid + t * THREADS;
                int r = idx >> 2, q = idx & 3;
                float4 vv = *reinterpret_cast<const float4*>(
                    B + (long long)(n0 + r) * ldb + k0 + q * 4);
                vv.x = f2tf32(vv.x); vv.y = f2tf32(vv.y);
                vv.z = f2tf32(vv.z); vv.w = f2tf32(vv.w);
                *reinterpret_cast<float4*>(&Bs[r * BS_STRIDE + q * 4]) = vv;
            }
        } else {
            constexpr int BIT = (BK * BN) / (THREADS * 4);
            constexpr int C4 = BN / 4;
#pragma unroll
            for (int t = 0; t < BIT; t++) {
                int idx = tid + t * THREADS;
                int r = idx / C4, cq = idx % C4;
                float4 vv = *reinterpret_cast<const float4*>(
                    B + (long long)(k0 + r) * ldb + n0 + cq * 4);
                vv.x = f2tf32(vv.x); vv.y = f2tf32(vv.y);
                vv.z = f2tf32(vv.z); vv.w = f2tf32(vv.w);
                *reinterpret_cast<float4*>(&Bs[r * BS_STRIDE + cq * 4]) = vv;
            }
        }
        __syncthreads();

#pragma unroll
        for (int ks = 0; ks < BK; ks += 8) {
            float4 af[MA];
            float2 bf[NA];
#pragma unroll
            for (int i = 0; i < MA; i++) {
                int r = wm + i * 16 + lr;
                af[i].x = As[r * AS_STRIDE + ks + lc];
                af[i].y = As[(r + 8) * AS_STRIDE + ks + lc];
                af[i].z = As[r * AS_STRIDE + ks + lc + 4];
                af[i].w = As[(r + 8) * AS_STRIDE + ks + lc + 4];
            }
#pragma unroll
            for (int j = 0; j < NA; j++) {
                int n = wn + j * 8 + lr;
                if (TB) {
                    bf[j].x = Bs[n * BS_STRIDE + ks + lc];
                    bf[j].y = Bs[n * BS_STRIDE + ks + lc + 4];
                } else {
                    bf[j].x = Bs[(ks + lc) * BS_STRIDE + n];
                    bf[j].y = Bs[(ks + lc + 4) * BS_STRIDE + n];
                }
            }
#pragma unroll
            for (int i = 0; i < MA; i++)
#pragma unroll
                for (int j = 0; j < NA; j++)
                    mma_tf32(acc[i][j], af[i], bf[j]);
        }
        __syncthreads();
    }

#pragma unroll
    for (int i = 0; i < MA; i++) {
        int r0 = m0 + wm + i * 16 + lr;
#pragma unroll
        for (int j = 0; j < NA; j++) {
            int cc = n0 + wn + j * 8 + lc * 2;
#pragma unroll
            for (int e = 0; e < 4; e++) {
                int r = (e < 2) ? r0 : r0 + 8;
                int c = cc + (e & 1);
                long long idx = (long long)r * ldc + c;
                float v = alpha * acc[i][j][e];
                if (S) v += beta * S[idx];
                if (bias) v += bias[c];
                C[idx] = v;
            }
        }
    }
}

// ======================= softmax variants ===================================
// fp32 in-place + e4m3(x256) copy
__global__ void __launch_bounds__(256) softmax2048_f8f(float* __restrict__ d,
                                                       uint8_t* __restrict__ h) {
    __shared__ float red[8];
    const size_t base = (size_t)blockIdx.x * 2048;
    const int tid = threadIdx.x;
    float4 v0 = *reinterpret_cast<float4*>(d + base + tid * 8);
    float4 v1 = *reinterpret_cast<float4*>(d + base + tid * 8 + 4);

    float m = fmaxf(fmaxf(fmaxf(v0.x, v0.y), fmaxf(v0.z, v0.w)),
                    fmaxf(fmaxf(v1.x, v1.y), fmaxf(v1.z, v1.w)));
#pragma unroll
    for (int o = 16; o > 0; o >>= 1) m = fmaxf(m, __shfl_xor_sync(0xffffffffu, m, o));
    if ((tid & 31) == 0) red[tid >> 5] = m;
    __syncthreads();
    m = red[0];
#pragma unroll
    for (int w = 1; w < 8; w++) m = fmaxf(m, red[w]);
    __syncthreads();

    v0.x = __expf(v0.x - m); v0.y = __expf(v0.y - m);
    v0.z = __expf(v0.z - m); v0.w = __expf(v0.w - m);
    v1.x = __expf(v1.x - m); v1.y = __expf(v1.y - m);
    v1.z = __expf(v1.z - m); v1.w = __expf(v1.w - m);

    float s = v0.x + v0.y + v0.z + v0.w + v1.x + v1.y + v1.z + v1.w;
#pragma unroll
    for (int o = 16; o > 0; o >>= 1) s += __shfl_xor_sync(0xffffffffu, s, o);
    if ((tid & 31) == 0) red[tid >> 5] = s;
    __syncthreads();
    s = red[0];
#pragma unroll
    for (int w = 1; w < 8; w++) s += red[w];
    float inv = 1.0f / s;

    v0.x *= inv; v0.y *= inv; v0.z *= inv; v0.w *= inv;
    v1.x *= inv; v1.y *= inv; v1.z *= inv; v1.w *= inv;
    *reinterpret_cast<float4*>(d + base + tid * 8) = v0;
    *reinterpret_cast<float4*>(d + base + tid * 8 + 4) = v1;

    uint2 o8;
    o8.x = (unsigned)f8pack2(256.f * v0.x, 256.f * v0.y) |
           ((unsigned)f8pack2(256.f * v0.z, 256.f * v0.w) << 16);
    o8.y = (unsigned)f8pack2(256.f * v1.x, 256.f * v1.y) |
           ((unsigned)f8pack2(256.f * v1.z, 256.f * v1.w) << 16);
    *reinterpret_cast<uint2*>(h + base + tid * 8) = o8;
}

// e4m3(x256)-only output
__global__ void __launch_bounds__(256) softmax2048_f8(const float* __restrict__ d,
                                                      uint8_t* __restrict__ h) {
    __shared__ float red[8];
    const size_t base = (size_t)blockIdx.x * 2048;
    const int tid = threadIdx.x;
    float4 v0 = *reinterpret_cast<const float4*>(d + base + tid * 8);
    float4 v1 = *reinterpret_cast<const float4*>(d + base + tid * 8 + 4);

    float m = fmaxf(fmaxf(fmaxf(v0.x, v0.y), fmaxf(v0.z, v0.w)),
                    fmaxf(fmaxf(v1.x, v1.y), fmaxf(v1.z, v1.w)));
#pragma unroll
    for (int o = 16; o > 0; o >>= 1) m = fmaxf(m, __shfl_xor_sync(0xffffffffu, m, o));
    if ((tid & 31) == 0) red[tid >> 5] = m;
    __syncthreads();
    m = red[0];
#pragma unroll
    for (int w = 1; w < 8; w++) m = fmaxf(m, red[w]);
    __syncthreads();

    v0.x = __expf(v0.x - m); v0.y = __expf(v0.y - m);
    v0.z = __expf(v0.z - m); v0.w = __expf(v0.w - m);
    v1.x = __expf(v1.x - m); v1.y = __expf(v1.y - m);
    v1.z = __expf(v1.z - m); v1.w = __expf(v1.w - m);

    float s = v0.x + v0.y + v0.z + v0.w + v1.x + v1.y + v1.z + v1.w;
#pragma unroll
    for (int o = 16; o > 0; o >>= 1) s += __shfl_xor_sync(0xffffffffu, s, o);
    if ((tid & 31) == 0) red[tid >> 5] = s;
    __syncthreads();
    s = red[0];
#pragma unroll
    for (int w = 1; w < 8; w++) s += red[w];
    float inv = 256.0f / s;

    uint2 o8;
    o8.x = (unsigned)f8pack2(inv * v0.x, inv * v0.y) |
           ((unsigned)f8pack2(inv * v0.z, inv * v0.w) << 16);
    o8.y = (unsigned)f8pack2(inv * v1.x, inv * v1.y) |
           ((unsigned)f8pack2(inv * v1.z, inv * v1.w) << 16);
    *reinterpret_cast<uint2*>(h + base + tid * 8) = o8;
}

// byte transpose per head: tile 32 rows x 128 cols -> 128 rows x 32 cols
__global__ void __launch_bounds__(256) transpose_f8(const uint8_t* __restrict__ in,
                                                    uint8_t* __restrict__ out) {
    __shared__ uint8_t t[128][52];   // 52 % 4 == 0 for u32 reads
    const size_t base = (size_t)blockIdx.z * N_TOK * N_TOK;
    const int x0 = blockIdx.x * 128, y0 = blockIdx.y * 32;
    const int tid = threadIdx.x, lane = tid & 31, w = tid >> 5;
#pragma unroll
    for (int r = w; r < 32; r += 8) {
        uchar4 v = *(const uchar4*)(in + base + (size_t)(y0 + r) * N_TOK + x0 + lane * 4);
        t[lane * 4 + 0][r] = v.x;
        t[lane * 4 + 1][r] = v.y;
        t[lane * 4 + 2][r] = v.z;
        t[lane * 4 + 3][r] = v.w;
    }
    __syncthreads();
    const int row = tid >> 1, h = tid & 1;
    const uint32_t* p = (const uint32_t*)&t[row][h * 16];
    uint4 val = make_uint4(p[0], p[1], p[2], p[3]);
    *(uint4*)(out + base + (size_t)(x0 + row) * N_TOK + y0 + h * 16) = val;
}

// ======================= host launcher ======================================
extern "C" void kernel_launch(void* const* d_in, const int* in_sizes, int n_in,
                              void* d_out, int out_size) {
    const float* X  = (const float*)d_in[0];
    const float* Wq = (const float*)d_in[1];
    const float* bq = (const float*)d_in[2];
    const float* Wk = (const float*)d_in[3];
    const float* bk = (const float*)d_in[4];
    const float* Wv = (const float*)d_in[5];
    const float* bv = (const float*)d_in[6];
    const float* Wo = (const float*)d_in[7];
    const float* bo = (const float*)d_in[8];

    float *q, *k, *v, *attn, *p0, *sim;
    uint8_t *a8, *b8, *bt8, *c8;
    cudaGetSymbolAddress((void**)&q, g_q);
    cudaGetSymbolAddress((void**)&k, g_k);
    cudaGetSymbolAddress((void**)&v, g_v);
    cudaGetSymbolAddress((void**)&attn, g_attn);
    cudaGetSymbolAddress((void**)&p0, g_p0);
    cudaGetSymbolAddress((void**)&sim, g_sim);
    cudaGetSymbolAddress((void**)&a8, g_a8);
    cudaGetSymbolAddress((void**)&b8, g_b8);
    cudaGetSymbolAddress((void**)&bt8, g_bt8);
    cudaGetSymbolAddress((void**)&c8, g_c8);

    float* out = (float*)d_out;
    const long long OUTE = (long long)N_TOK * D_EMB;
    const long long PE   = (long long)N_HEAD * N_TOK * N_TOK;
    float* pdst = ((long long)out_size >= OUTE + PE) ? out + OUTE : p0;
    const long long PS = (long long)N_TOK * N_TOK;

    static bool s_init = false;
    static cudaStream_t s1, s2;
    static cudaEvent_t evRoot, evK, ev1, ev2;
    if (!s_init) {
        cudaStreamCreateWithFlags(&s1, cudaStreamNonBlocking);
        cudaStreamCreateWithFlags(&s2, cudaStreamNonBlocking);
        cudaEventCreateWithFlags(&evRoot, cudaEventDisableTiming);
        cudaEventCreateWithFlags(&evK,    cudaEventDisableTiming);
        cudaEventCreateWithFlags(&ev1,    cudaEventDisableTiming);
        cudaEventCreateWithFlags(&ev2,    cudaEventDisableTiming);
        cudaFuncSetAttribute(f8_diffuse<true>,
                             cudaFuncAttributeMaxDynamicSharedMemorySize, FSMEM);
        cudaFuncSetAttribute(f8_diffuse<false>,
                             cudaFuncAttributeMaxDynamicSharedMemorySize, FSMEM);
        s_init = true;
    }

    dim3 blk256(256), blk128(128);
    dim3 gproj(D_EMB / 128, N_TOK / 128, 1);
    dim3 gnt(N_TOK / 128, N_TOK / 128, N_HEAD);

    // fork point
    cudaEventRecord(evRoot, 0);
    cudaStreamWaitEvent(s1, evRoot, 0);
    cudaStreamWaitEvent(s2, evRoot, 0);

    // s1: Q projection (needs only X)
    gemm_tf32_kernel<128, 128, 64, 32, false><<<gproj, blk256, 0, s1>>>(
        X, Wq, nullptr, bq, q, D_EMB, D_EMB, D_EMB, D_EMB, 0, 0, 0, 0, 1.0f, 0.0f);

    // default: K projection, then V projection (V overlaps s1/s2 work)
    gemm_tf32_kernel<128, 128, 64, 32, false><<<gproj, blk256>>>(
        X, Wk, nullptr, bk, k, D_EMB, D_EMB, D_EMB, D_EMB, 0, 0, 0, 0, 1.0f, 0.0f);
    cudaEventRecord(evK, 0);
    gemm_tf32_kernel<128, 128, 64, 32, false><<<gproj, blk256>>>(
        X, Wv, nullptr, bv, v, D_EMB, D_EMB, D_EMB, D_EMB, 0, 0, 0, 0, 1.0f, 0.0f);

    // s1: scores = Q K^T / 8 -> softmax -> p0 fp32 + a8 fp8
    cudaStreamWaitEvent(s1, evK, 0);
    gemm_tf32_kernel<128, 128, 64, 32, true><<<gnt, blk256, 0, s1>>>(
        q, k, nullptr, nullptr, p0, HD, D_EMB, D_EMB, N_TOK, HD, HD, PS, 0, 0.125f, 0.0f);
    softmax2048_f8f<<<N_HEAD * N_TOK, blk256, 0, s1>>>(p0, a8);
    cudaEventRecord(ev1, s1);

    // s2: sim = K K^T / 32 -> softmax fp8 -> transpose
    cudaStreamWaitEvent(s2, evK, 0);
    gemm_tf32_kernel<128, 128, 64, 32, true><<<gnt, blk256, 0, s2>>>(
        k, k, nullptr, nullptr, sim, HD, D_EMB, D_EMB, N_TOK, HD, HD, PS, 0, 0.03125f, 0.0f);
    softmax2048_f8<<<N_HEAD * N_TOK, blk256, 0, s2>>>(sim, b8);
    transpose_f8<<<dim3(16, 64, N_HEAD), blk256, 0, s2>>>(b8, bt8);
    cudaEventRecord(ev2, s2);

    // join, then diffusion on default stream
    cudaStreamWaitEvent(0, ev1, 0);
    cudaStreamWaitEvent(0, ev2, 0);
    {
        dim3 g(N_TOK / FBN, N_TOK / FBM, N_HEAD);
        f8_diffuse<true ><<<g, blk256, FSMEM>>>(a8, bt8, p0, nullptr, c8);
        f8_diffuse<false><<<g, blk256, FSMEM>>>(c8, bt8, p0, pdst, nullptr);
    }

    // attn_h = p_h @ V_h (TF32)
    {
        dim3 g(1, N_TOK / 128, N_HEAD);
        gemm_tf32_kernel<128, 64, 64, 32, false><<<g, blk128>>>(
            pdst, v, nullptr, nullptr, attn, N_TOK, N_TOK, D_EMB, D_EMB,
            PS, HD, HD, 0, 1.0f, 0.0f);
    }

    // out = attn @ Wo + bo (TF32)
    gemm_tf32_kernel<128, 128, 64, 32, false><<<gproj, blk256>>>(
        attn, Wo, nullptr, bo, out, D_EMB, D_EMB, D_EMB, D_EMB, 0, 0, 0, 0, 1.0f, 0.0f);
}

// round 5
// speedup vs baseline: 1.8867x; 1.0093x over previous
#include <cuda_runtime.h>
#include <cuda_bf16.h>
#include <cuda_fp16.h>
#include <cstdint>

// ----------------------------------------------------------------------------
// StableQGFD layer.  p = 0.95*p0 + p0 @ S,  S = 0.0475*P + 0.0025*P^2.
// S^T computed as 0.0475*Pt + 0.0025*(Pt@Pt) from (A=Pt8, Bt=P8) — no
// transposes needed (sim = K K^T is symmetric, so Pt comes straight from sim).
// Both N^3 GEMMs: legacy mma.sync e4m3 with ldmatrix fragment loads.
// ----------------------------------------------------------------------------

#define N_TOK 2048
#define D_EMB 1024
#define N_HEAD 16
#define HD 64

__device__ float g_q[(size_t)N_TOK * D_EMB];
__device__ float g_k[(size_t)N_TOK * D_EMB];
__device__ float g_v[(size_t)N_TOK * D_EMB];
__device__ float g_attn[(size_t)N_TOK * D_EMB];
__device__ float g_p0 [(size_t)N_HEAD * N_TOK * N_TOK];    // p0 fp32 (softmax'd)
__device__ float g_sim[(size_t)N_HEAD * N_TOK * N_TOK];    // raw KK^T logits
__device__ float2  g_st[(size_t)N_HEAD * N_TOK];           // {m, 256/s} per sim row
__device__ uint8_t g_a8 [(size_t)N_HEAD * N_TOK * N_TOK];  // 256*p0  e4m3
__device__ uint8_t g_P8 [(size_t)N_HEAD * N_TOK * N_TOK];  // 256*P   e4m3
__device__ uint8_t g_Pt8[(size_t)N_HEAD * N_TOK * N_TOK];  // 256*P^T e4m3
__device__ uint8_t g_St8[(size_t)N_HEAD * N_TOK * N_TOK];  // 8192*S^T e4m3

__device__ __forceinline__ float f2tf32(float x) {
    asm("cvt.rna.tf32.f32 %0, %0;" : "+f"(x));
    return x;
}

__device__ __forceinline__ unsigned short f8pack2(float lo, float hi) {
    unsigned short r;
    asm("cvt.rn.satfinite.e4m3x2.f32 %0, %1, %2;" : "=h"(r) : "f"(hi), "f"(lo));
    return r;
}

__device__ __forceinline__ float2 f8unpack2(unsigned short v) {
    unsigned hh;
    asm("cvt.rn.f16x2.e4m3x2 %0, %1;" : "=r"(hh) : "h"(v));
    __half2 h2 = *reinterpret_cast<__half2*>(&hh);
    return make_float2(__low2float(h2), __high2float(h2));
}

__device__ __forceinline__ void mma_tf32(float* c, const float4& a, const float2& b) {
    unsigned a0 = __float_as_uint(a.x), a1 = __float_as_uint(a.y);
    unsigned a2 = __float_as_uint(a.z), a3 = __float_as_uint(a.w);
    unsigned b0 = __float_as_uint(b.x), b1 = __float_as_uint(b.y);
    asm volatile(
        "mma.sync.aligned.m16n8k8.row.col.f32.tf32.tf32.f32 "
        "{%0,%1,%2,%3},{%4,%5,%6,%7},{%8,%9},{%0,%1,%2,%3};"
        : "+f"(c[0]), "+f"(c[1]), "+f"(c[2]), "+f"(c[3])
        : "r"(a0), "r"(a1), "r"(a2), "r"(a3), "r"(b0), "r"(b1));
}

__device__ __forceinline__ void mma_e4m3(float* c, const unsigned* a, const unsigned* b) {
    asm volatile(
        "mma.sync.aligned.m16n8k32.row.col.f32.e4m3.e4m3.f32 "
        "{%0,%1,%2,%3},{%4,%5,%6,%7},{%8,%9},{%0,%1,%2,%3};"
        : "+f"(c[0]), "+f"(c[1]), "+f"(c[2]), "+f"(c[3])
        : "r"(a[0]), "r"(a[1]), "r"(a[2]), "r"(a[3]), "r"(b[0]), "r"(b[1]));
}

#define LDSM4(r0, r1, r2, r3, addr) \
    asm volatile("ldmatrix.sync.aligned.m8n8.x4.shared.b16 {%0,%1,%2,%3}, [%4];" \
                 : "=r"(r0), "=r"(r1), "=r"(r2), "=r"(r3) : "r"(addr))

// ======================= FP8 GEMM (diffusion path) ==========================
// acc = A8 @ Bt8^T per head (blockIdx.z); A8/Bt8 e4m3 row-major [2048,2048].
// MODE 0 (S build):  C8[i][j] = f8( 1.52*dec(A8[i][j]) + 3.125e-4*acc )
//                    (A8 = 256*Pt, acc = 65536*(Pt@Pt), C8 = 8192*S^T)
// MODE 1 (final p):  Cf = 0.95*SRCf + acc/2097152   (fp32 out)
#define FBM 128
#define FBN 256
#define FBK 64
#define FST 4
#define FROW 80
#define FSTAGE_BYTES ((FBM + FBN) * FROW)
#define FSMEM (FST * FSTAGE_BYTES)
#define FNIT (N_TOK / FBK)

template <int MODE>
__global__ void __launch_bounds__(256, 1)
f8_gemm(const uint8_t* __restrict__ A, const uint8_t* __restrict__ Bt,
        const float* __restrict__ SRC, float* __restrict__ Cf,
        uint8_t* __restrict__ C8)
{
    extern __shared__ __align__(128) uint8_t sm[];
    constexpr long long PS = (long long)N_TOK * N_TOK;
    const int z = blockIdx.z;
    A += z * PS; Bt += z * PS;
    if constexpr (MODE == 1) { SRC += z * PS; Cf += z * PS; }
    else                     { C8 += z * PS; }

    const int m0 = blockIdx.y * FBM, n0 = blockIdx.x * FBN;
    const int tid = threadIdx.x, lane = tid & 31, warp = tid >> 5;
    const int wm = (warp >> 2) * 64, wn = (warp & 3) * 64;
    const int lr = lane >> 2, lc = lane & 3;

    auto load_stage = [&](int s, int kc) {
        uint8_t* base = sm + s * FSTAGE_BYTES;
        const int ke = kc * FBK;
#pragma unroll
        for (int t = 0; t < 2; t++) {
            int idx = tid + t * 256;
            int r = idx >> 2, c = idx & 3;
            unsigned dst = (unsigned)__cvta_generic_to_shared(base + r * FROW + c * 16);
            const uint8_t* src = A + (long long)(m0 + r) * N_TOK + ke + c * 16;
            asm volatile("cp.async.cg.shared.global [%0], [%1], 16;" :: "r"(dst), "l"(src));
        }
        uint8_t* bbase = base + FBM * FROW;
#pragma unroll
        for (int t = 0; t < 4; t++) {
            int idx = tid + t * 256;
            int r = idx >> 2, c = idx & 3;
            unsigned dst = (unsigned)__cvta_generic_to_shared(bbase + r * FROW + c * 16);
            const uint8_t* src = Bt + (long long)(n0 + r) * N_TOK + ke + c * 16;
            asm volatile("cp.async.cg.shared.global [%0], [%1], 16;" :: "r"(dst), "l"(src));
        }
        asm volatile("cp.async.commit_group;");
    };

    // ldmatrix per-lane byte offsets (within stage)
    const unsigned smbase = (unsigned)__cvta_generic_to_shared(sm);
    const unsigned la = (unsigned)((wm + (lane & 15)) * FROW + ((lane >> 4) << 4));
    const unsigned lb = (unsigned)((wn + ((lane >> 1) & 8) + (lane & 7)) * FROW
                                   + ((lane & 8) << 1));

    float acc[4][8][4] = {};

    for (int p = 0; p < FST - 1; p++) load_stage(p, p);

    for (int i = 0; i < FNIT; i++) {
        if (i + FST - 1 < FNIT) {
            asm volatile("cp.async.wait_group 2;");
            __syncthreads();
            load_stage((i + FST - 1) % FST, i + FST - 1);
        } else {
            asm volatile("cp.async.wait_group 0;");
            __syncthreads();
        }
        const unsigned abase = smbase + (i % FST) * FSTAGE_BYTES;
        const unsigned bbase = abase + FBM * FROW;
#pragma unroll
        for (int ks = 0; ks < FBK; ks += 32) {
            unsigned af[4][4], bf[8][2];
#pragma unroll
            for (int ii = 0; ii < 4; ii++)
                LDSM4(af[ii][0], af[ii][1], af[ii][2], af[ii][3],
                      abase + la + ii * (16 * FROW) + ks);
#pragma unroll
            for (int jp = 0; jp < 4; jp++)
                LDSM4(bf[2 * jp][0], bf[2 * jp][1], bf[2 * jp + 1][0], bf[2 * jp + 1][1],
                      bbase + lb + jp * (16 * FROW) + ks);
#pragma unroll
            for (int ii = 0; ii < 4; ii++)
#pragma unroll
                for (int j = 0; j < 8; j++)
                    mma_e4m3(acc[ii][j], af[ii], bf[j]);
        }
    }

#pragma unroll
    for (int ii = 0; ii < 4; ii++) {
        int r0 = m0 + wm + ii * 16 + lr;
#pragma unroll
        for (int j = 0; j < 8; j++) {
            int c0 = n0 + wn + j * 8 + 2 * lc;
            long long i0 = (long long)r0 * N_TOK + c0;
            long long i1 = i0 + 8LL * N_TOK;
            if constexpr (MODE == 0) {
                float2 q0 = f8unpack2(*(const unsigned short*)(A + i0));
                float2 q1 = f8unpack2(*(const unsigned short*)(A + i1));
                float t0 = 1.52f * q0.x + 3.125e-4f * acc[ii][j][0];
                float t1 = 1.52f * q0.y + 3.125e-4f * acc[ii][j][1];
                float t2 = 1.52f * q1.x + 3.125e-4f * acc[ii][j][2];
                float t3 = 1.52f * q1.y + 3.125e-4f * acc[ii][j][3];
                *(unsigned short*)(C8 + i0) = f8pack2(t0, t1);
                *(unsigned short*)(C8 + i1) = f8pack2(t2, t3);
            } else {
                constexpr float AEF = 1.0f / 2097152.0f;
                float2 s0 = *(const float2*)(SRC + i0);
                float2 s1 = *(const float2*)(SRC + i1);
                float2 o0, o1;
                o0.x = 0.95f * s0.x + AEF * acc[ii][j][0];
                o0.y = 0.95f * s0.y + AEF * acc[ii][j][1];
                o1.x = 0.95f * s1.x + AEF * acc[ii][j][2];
                o1.y = 0.95f * s1.y + AEF * acc[ii][j][3];
                *(float2*)(Cf + i0) = o0;
                *(float2*)(Cf + i1) = o1;
            }
        }
    }
}

// ======================= TF32 general GEMM ==================================
template <int BM, int BN, int WM, int WN, bool TB>
__global__ void __launch_bounds__((BM / WM) * (BN / WN) * 32, 2)
gemm_tf32_kernel(const float* __restrict__ A, const float* __restrict__ B,
                 const float* __restrict__ SRC, const float* __restrict__ bias,
                 float* __restrict__ C,
                 int K, int lda, int ldb, int ldc,
                 long long sA, long long sB, long long sC, long long sS,
                 float alpha, float beta) {
    constexpr int BK = 16;
    constexpr int THREADS = (BM / WM) * (BN / WN) * 32;
    constexpr int MA = WM / 16;
    constexpr int NA = WN / 8;
    constexpr int AS_STRIDE = BK + 4;
    constexpr int BS_ROWS   = TB ? BN : BK;
    constexpr int BS_STRIDE = TB ? (BK + 4) : (BN + 8);

    __shared__ float As[BM * AS_STRIDE];
    __shared__ float Bs[BS_ROWS * BS_STRIDE];

    const int z = blockIdx.z;
    A += (long long)z * sA;
    B += (long long)z * sB;
    C += (long long)z * sC;
    const float* S = SRC ? SRC + (long long)z * sS : nullptr;

    const int m0 = blockIdx.y * BM;
    const int n0 = blockIdx.x * BN;
    const int tid = threadIdx.x;
    const int lane = tid & 31, warp = tid >> 5;
    constexpr int WARPS_N = BN / WN;
    const int wm = (warp / WARPS_N) * WM;
    const int wn = (warp % WARPS_N) * WN;
    const int lr = lane >> 2;
    const int lc = lane & 3;

    float acc[MA][NA][4];
#pragma unroll
    for (int i = 0; i < MA; i++)
#pragma unroll
        for (int j = 0; j < NA; j++) {
            acc[i][j][0] = 0.f; acc[i][j][1] = 0.f;
            acc[i][j][2] = 0.f; acc[i][j][3] = 0.f;
        }

    for (int k0 = 0; k0 < K; k0 += BK) {
        constexpr int AIT = (BM * BK) / (THREADS * 4);
#pragma unroll
        for (int t = 0; t < AIT; t++) {
            int idx = tid + t * THREADS;
            int r = idx >> 2, q = idx & 3;
            float4 vv = *reinterpret_cast<const float4*>(
                A + (long long)(m0 + r) * lda + k0 + q * 4);
            vv.x = f2tf32(vv.x); vv.y = f2tf32(vv.y);
            vv.z = f2tf32(vv.z); vv.w = f2tf32(vv.w);
            *reinterpret_cast<float4*>(&As[r * AS_STRIDE + q * 4]) = vv;
        }
        if (TB) {
            constexpr int BIT = (BN * BK) / (THREADS * 4);
#pragma unroll
            for (int t = 0; t < BIT; t++) {
                int idx = tid + t * THREADS;
                int r = idx >> 2, q = idx & 3;
                float4 vv = *reinterpret_cast<const float4*>(
                    B + (long long)(n0 + r) * ldb + k0 + q * 4);
                vv.x = f2tf32(vv.x); vv.y = f2tf32(vv.y);
                vv.z = f2tf32(vv.z); vv.w = f2tf32(vv.w);
                *reinterpret_cast<float4*>(&Bs[r * BS_STRIDE + q * 4]) = vv;
            }
        } else {
            constexpr int BIT = (BK * BN) / (THREADS * 4);
            constexpr int C4 = BN / 4;
#pragma unroll
            for (int t = 0; t < BIT; t++) {
                int idx = tid + t * THREADS;
                int r = idx / C4, cq = idx % C4;
                float4 vv = *reinterpret_cast<const float4*>(
                    B + (long long)(k0 + r) * ldb + n0 + cq * 4);
                vv.x = f2tf32(vv.x); vv.y = f2tf32(vv.y);
                vv.z = f2tf32(vv.z); vv.w = f2tf32(vv.w);
                *reinterpret_cast<float4*>(&Bs[r * BS_STRIDE + cq * 4]) = vv;
            }
        }
        __syncthreads();

#pragma unroll
        for (int ks = 0; ks < BK; ks += 8) {
            float4 af[MA];
            float2 bf[NA];
#pragma unroll
            for (int i = 0; i < MA; i++) {
                int r = wm + i * 16 + lr;
                af[i].x = As[r * AS_STRIDE + ks + lc];
                af[i].y = As[(r + 8) * AS_STRIDE + ks + lc];
                af[i].z = As[r * AS_STRIDE + ks + lc + 4];
                af[i].w = As[(r + 8) * AS_STRIDE + ks + lc + 4];
            }
#pragma unroll
            for (int j = 0; j < NA; j++) {
                int n = wn + j * 8 + lr;
                if (TB) {
                    bf[j].x = Bs[n * BS_STRIDE + ks + lc];
                    bf[j].y = Bs[n * BS_STRIDE + ks + lc + 4];
                } else {
                    bf[j].x = Bs[(ks + lc) * BS_STRIDE + n];
                    bf[j].y = Bs[(ks + lc + 4) * BS_STRIDE + n];
                }
            }
#pragma unroll
            for (int i = 0; i < MA; i++)
#pragma unroll
                for (int j = 0; j < NA; j++)
                    mma_tf32(acc[i][j], af[i], bf[j]);
        }
        __syncthreads();
    }

#pragma unroll
    for (int i = 0; i < MA; i++) {
        int r0 = m0 + wm + i * 16 + lr;
#pragma unroll
        for (int j = 0; j < NA; j++) {
            int cc = n0 + wn + j * 8 + lc * 2;
#pragma unroll
            for (int e = 0; e < 4; e++) {
                int r = (e < 2) ? r0 : r0 + 8;
                int c = cc + (e & 1);
                long long idx = (long long)r * ldc + c;
                float v = alpha * acc[i][j][e];
                if (S) v += beta * S[idx];
                if (bias) v += bias[c];
                C[idx] = v;
            }
        }
    }
}

// ======================= softmax / stats / P write ==========================
// p0 softmax: fp32 in-place + 256x e4m3 copy
__global__ void __launch_bounds__(256) softmax2048_f8f(float* __restrict__ d,
                                                       uint8_t* __restrict__ h) {
    __shared__ float red[8];
    const size_t base = (size_t)blockIdx.x * 2048;
    const int tid = threadIdx.x;
    float4 v0 = *reinterpret_cast<float4*>(d + base + tid * 8);
    float4 v1 = *reinterpret_cast<float4*>(d + base + tid * 8 + 4);

    float m = fmaxf(fmaxf(fmaxf(v0.x, v0.y), fmaxf(v0.z, v0.w)),
                    fmaxf(fmaxf(v1.x, v1.y), fmaxf(v1.z, v1.w)));
#pragma unroll
    for (int o = 16; o > 0; o >>= 1) m = fmaxf(m, __shfl_xor_sync(0xffffffffu, m, o));
    if ((tid & 31) == 0) red[tid >> 5] = m;
    __syncthreads();
    m = red[0];
#pragma unroll
    for (int w = 1; w < 8; w++) m = fmaxf(m, red[w]);
    __syncthreads();

    v0.x = __expf(v0.x - m); v0.y = __expf(v0.y - m);
    v0.z = __expf(v0.z - m); v0.w = __expf(v0.w - m);
    v1.x = __expf(v1.x - m); v1.y = __expf(v1.y - m);
    v1.z = __expf(v1.z - m); v1.w = __expf(v1.w - m);

    float s = v0.x + v0.y + v0.z + v0.w + v1.x + v1.y + v1.z + v1.w;
#pragma unroll
    for (int o = 16; o > 0; o >>= 1) s += __shfl_xor_sync(0xffffffffu, s, o);
    if ((tid & 31) == 0) red[tid >> 5] = s;
    __syncthreads();
    s = red[0];
#pragma unroll
    for (int w = 1; w < 8; w++) s += red[w];
    float inv = 1.0f / s;

    v0.x *= inv; v0.y *= inv; v0.z *= inv; v0.w *= inv;
    v1.x *= inv; v1.y *= inv; v1.z *= inv; v1.w *= inv;
    *reinterpret_cast<float4*>(d + base + tid * 8) = v0;
    *reinterpret_cast<float4*>(d + base + tid * 8 + 4) = v1;

    uint2 o8;
    o8.x = (unsigned)f8pack2(256.f * v0.x, 256.f * v0.y) |
           ((unsigned)f8pack2(256.f * v0.z, 256.f * v0.w) << 16);
    o8.y = (unsigned)f8pack2(256.f * v1.x, 256.f * v1.y) |
           ((unsigned)f8pack2(256.f * v1.z, 256.f * v1.w) << 16);
    *reinterpret_cast<uint2*>(h + base + tid * 8) = o8;
}

// per-row stats of sim: {m, 256/sum exp(x-m)}
__global__ void __launch_bounds__(256) simstats(const float* __restrict__ d,
                                                float2* __restrict__ st) {
    __shared__ float red[8];
    const size_t base = (size_t)blockIdx.x * 2048;
    const int tid = threadIdx.x;
    float4 v0 = *reinterpret_cast<const float4*>(d + base + tid * 8);
    float4 v1 = *reinterpret_cast<const float4*>(d + base + tid * 8 + 4);

    float m = fmaxf(fmaxf(fmaxf(v0.x, v0.y), fmaxf(v0.z, v0.w)),
                    fmaxf(fmaxf(v1.x, v1.y), fmaxf(v1.z, v1.w)));
#pragma unroll
    for (int o = 16; o > 0; o >>= 1) m = fmaxf(m, __shfl_xor_sync(0xffffffffu, m, o));
    if ((tid & 31) == 0) red[tid >> 5] = m;
    __syncthreads();
    m = red[0];
#pragma unroll
    for (int w = 1; w < 8; w++) m = fmaxf(m, red[w]);
    __syncthreads();

    float s = __expf(v0.x - m) + __expf(v0.y - m) + __expf(v0.z - m) + __expf(v0.w - m)
            + __expf(v1.x - m) + __expf(v1.y - m) + __expf(v1.z - m) + __expf(v1.w - m);
#pragma unroll
    for (int o = 16; o > 0; o >>= 1) s += __shfl_xor_sync(0xffffffffu, s, o);
    if ((tid & 31) == 0) red[tid >> 5] = s;
    __syncthreads();
    if (tid == 0) {
        s = red[0];
#pragma unroll
        for (int w = 1; w < 8; w++) s += red[w];
        st[blockIdx.x] = make_float2(m, 256.0f / s);
    }
}

// P8[i][j] = exp(sim-m_i)*rs_i ; Pt8[i][j] = exp(sim-m_j)*rs_j  (sim symmetric)
__global__ void __launch_bounds__(256) write_ppt(const float* __restrict__ sim,
                                                 const float2* __restrict__ st,
                                                 uint8_t* __restrict__ P8,
                                                 uint8_t* __restrict__ Pt8) {
    const size_t rb = blockIdx.x;                  // global row, 0..32767
    const size_t base = rb * 2048;
    const float2* sth = st + ((rb >> 11) << 11);   // head stats base
    const float2 sti = st[rb];
    const int j0 = threadIdx.x * 8;

    float4 x0 = *reinterpret_cast<const float4*>(sim + base + j0);
    float4 x1 = *reinterpret_cast<const float4*>(sim + base + j0 + 4);

    // P row
    float p0v = __expf(x0.x - sti.x) * sti.y;
    float p1v = __expf(x0.y - sti.x) * sti.y;
    float p2v = __expf(x0.z - sti.x) * sti.y;
    float p3v = __expf(x0.w - sti.x) * sti.y;
    float p4v = __expf(x1.x - sti.x) * sti.y;
    float p5v = __expf(x1.y - sti.x) * sti.y;
    float p6v = __expf(x1.z - sti.x) * sti.y;
    float p7v = __expf(x1.w - sti.x) * sti.y;
    uint2 pr;
    pr.x = (unsigned)f8pack2(p0v, p1v) | ((unsigned)f8pack2(p2v, p3v) << 16);
    pr.y = (unsigned)f8pack2(p4v, p5v) | ((unsigned)f8pack2(p6v, p7v) << 16);
    *reinterpret_cast<uint2*>(P8 + base + j0) = pr;

    // Pt row (per-column stats)
    float2 sj0 = sth[j0 + 0], sj1 = sth[j0 + 1], sj2 = sth[j0 + 2], sj3 = sth[j0 + 3];
    float2 sj4 = sth[j0 + 4], sj5 = sth[j0 + 5], sj6 = sth[j0 + 6], sj7 = sth[j0 + 7];
    float t0 = __expf(x0.x - sj0.x) * sj0.y;
    float t1 = __expf(x0.y - sj1.x) * sj1.y;
    float t2 = __expf(x0.z - sj2.x) * sj2.y;
    float t3 = __expf(x0.w - sj3.x) * sj3.y;
    float t4 = __expf(x1.x - sj4.x) * sj4.y;
    float t5 = __expf(x1.y - sj5.x) * sj5.y;
    float t6 = __expf(x1.z - sj6.x) * sj6.y;
    float t7 = __expf(x1.w - sj7.x) * sj7.y;
    uint2 tr;
    tr.x = (unsigned)f8pack2(t0, t1) | ((unsigned)f8pack2(t2, t3) << 16);
    tr.y = (unsigned)f8pack2(t4, t5) | ((unsigned)f8pack2(t6, t7) << 16);
    *reinterpret_cast<uint2*>(Pt8 + base + j0) = tr;
}

// ======================= host launcher ======================================
extern "C" void kernel_launch(void* const* d_in, const int* in_sizes, int n_in,
                              void* d_out, int out_size) {
    const float* X  = (const float*)d_in[0];
    const float* Wq = (const float*)d_in[1];
    const float* bq = (const float*)d_in[2];
    const float* Wk = (const float*)d_in[3];
    const float* bk = (const float*)d_in[4];
    const float* Wv = (const float*)d_in[5];
    const float* bv = (const float*)d_in[6];
    const float* Wo = (const float*)d_in[7];
    const float* bo = (const float*)d_in[8];

    float *q, *k, *v, *attn, *p0, *sim;
    float2* st;
    uint8_t *a8, *P8, *Pt8, *St8;
    cudaGetSymbolAddress((void**)&q, g_q);
    cudaGetSymbolAddress((void**)&k, g_k);
    cudaGetSymbolAddress((void**)&v, g_v);
    cudaGetSymbolAddress((void**)&attn, g_attn);
    cudaGetSymbolAddress((void**)&p0, g_p0);
    cudaGetSymbolAddress((void**)&sim, g_sim);
    cudaGetSymbolAddress((void**)&st, g_st);
    cudaGetSymbolAddress((void**)&a8, g_a8);
    cudaGetSymbolAddress((void**)&P8, g_P8);
    cudaGetSymbolAddress((void**)&Pt8, g_Pt8);
    cudaGetSymbolAddress((void**)&St8, g_St8);

    float* out = (float*)d_out;
    const long long OUTE = (long long)N_TOK * D_EMB;
    const long long PE   = (long long)N_HEAD * N_TOK * N_TOK;
    float* pdst = ((long long)out_size >= OUTE + PE) ? out + OUTE : p0;
    const long long PS = (long long)N_TOK * N_TOK;

    static bool s_init = false;
    static cudaStream_t s1;
    static cudaEvent_t evRoot, evK, ev1;
    if (!s_init) {
        cudaStreamCreateWithFlags(&s1, cudaStreamNonBlocking);
        cudaEventCreateWithFlags(&evRoot, cudaEventDisableTiming);
        cudaEventCreateWithFlags(&evK,    cudaEventDisableTiming);
        cudaEventCreateWithFlags(&ev1,    cudaEventDisableTiming);
        cudaFuncSetAttribute(f8_gemm<0>,
                             cudaFuncAttributeMaxDynamicSharedMemorySize, FSMEM);
        cudaFuncSetAttribute(f8_gemm<1>,
                             cudaFuncAttributeMaxDynamicSharedMemorySize, FSMEM);
        s_init = true;
    }

    dim3 blk256(256), blk128(128);
    dim3 gproj(D_EMB / 128, N_TOK / 128, 1);
    dim3 gnt(N_TOK / 128, N_TOK / 128, N_HEAD);
    dim3 gf8(N_TOK / FBN, N_TOK / FBM, N_HEAD);

    cudaEventRecord(evRoot, 0);
    cudaStreamWaitEvent(s1, evRoot, 0);

    // (1) K projection (default stream)
    gemm_tf32_kernel<128, 128, 64, 32, false><<<gproj, blk256>>>(
        X, Wk, nullptr, bk, k, D_EMB, D_EMB, D_EMB, D_EMB, 0, 0, 0, 0, 1.0f, 0.0f);
    cudaEventRecord(evK, 0);

    // (2) Q projection (s1, overlaps sim chain)
    gemm_tf32_kernel<128, 128, 64, 32, false><<<gproj, blk256, 0, s1>>>(
        X, Wq, nullptr, bq, q, D_EMB, D_EMB, D_EMB, D_EMB, 0, 0, 0, 0, 1.0f, 0.0f);

    // (3) sim = K K^T / 32   (4) row stats   (5) P8 + Pt8
    gemm_tf32_kernel<128, 128, 64, 32, true><<<gnt, blk256>>>(
        k, k, nullptr, nullptr, sim, HD, D_EMB, D_EMB, N_TOK, HD, HD, PS, 0, 0.03125f, 0.0f);
    simstats<<<N_HEAD * N_TOK, blk256>>>(sim, st);
    write_ppt<<<N_HEAD * N_TOK, blk256>>>(sim, st, P8, Pt8);

    // (6) S^T = 0.0475*Pt + 0.0025*Pt@Pt   [PROFILED LAUNCH]
    f8_gemm<0><<<gf8, blk256, FSMEM>>>(Pt8, P8, nullptr, nullptr, St8);

    // s1: (7) scores  (8) softmax p0  (9) V projection
    cudaStreamWaitEvent(s1, evK, 0);
    gemm_tf32_kernel<128, 128, 64, 32, true><<<gnt, blk256, 0, s1>>>(
        q, k, nullptr, nullptr, p0, HD, D_EMB, D_EMB, N_TOK, HD, HD, PS, 0, 0.125f, 0.0f);
    softmax2048_f8f<<<N_HEAD * N_TOK, blk256, 0, s1>>>(p0, a8);
    gemm_tf32_kernel<128, 128, 64, 32, false><<<gproj, blk256, 0, s1>>>(
        X, Wv, nullptr, bv, v, D_EMB, D_EMB, D_EMB, D_EMB, 0, 0, 0, 0, 1.0f, 0.0f);
    cudaEventRecord(ev1, s1);

    // (10) p = 0.95*p0 + p0 @ S  (fp32 out)
    cudaStreamWaitEvent(0, ev1, 0);
    f8_gemm<1><<<gf8, blk256, FSMEM>>>(a8, St8, p0, pdst, nullptr);

    // (11) attn_h = p_h @ V_h
    {
        dim3 g(1, N_TOK / 128, N_HEAD);
        gemm_tf32_kernel<128, 64, 64, 32, false><<<g, blk128>>>(
            pdst, v, nullptr, nullptr, attn, N_TOK, N_TOK, D_EMB, D_EMB,
            PS, HD, HD, 0, 1.0f, 0.0f);
    }

    // (12) out = attn @ Wo + bo
    gemm_tf32_kernel<128, 128, 64, 32, false><<<gproj, blk256>>>(
        attn, Wo, nullptr, bo, out, D_EMB, D_EMB, D_EMB, D_EMB, 0, 0, 0, 0, 1.0f, 0.0f);
}